// round 5
// baseline (speedup 1.0000x reference)
#include <cuda_runtime.h>
#include <cstdint>

#define NN  40000
#define EE  640000
#define NNZ (EE + NN)   // 680000 (edges + self-loops)

#define NSCAN_BLK 40    // 40 blocks x 1000 elements = NN
#define SCAN_CH   1000

typedef unsigned long long ull;

// ---------------- scratch (device globals — no runtime allocation) ----------
__device__ __align__(256) float g_buf0[NN * 128];
__device__ __align__(256) float g_buf1[NN * 128];
__device__ float g_dinv[NN];
__device__ int   g_deg[NN];
__device__ int   g_rowptr[NN + 1];
__device__ int   g_cursor[NN];
__device__ __align__(16) int2 g_adj[NNZ];   // {col, bitcast(weight)}
__device__ int   g_blocksum[NSCAN_BLK];
__device__ int   g_blockoff[NSCAN_BLK];

// ---------------- packed fp32x2 helpers (sm_10x) -----------------------------
__device__ __forceinline__ ull ffma2(ull a, ull b, ull c) {
  ull d;
  asm("fma.rn.f32x2 %0, %1, %2, %3;" : "=l"(d) : "l"(a), "l"(b), "l"(c));
  return d;
}
__device__ __forceinline__ float hsum2(ull v) {
  float lo, hi;
  asm("mov.b64 {%0, %1}, %2;" : "=f"(lo), "=f"(hi) : "l"(v));
  return lo + hi;
}
__device__ __forceinline__ ull pack2(float lo, float hi) {
  ull v;
  asm("mov.b64 %0, {%1, %2};" : "=l"(v) : "f"(lo), "f"(hi));
  return v;
}

// ---------------- preprocessing ---------------------------------------------
__global__ void init_deg_kernel() {
  int i = blockIdx.x * 256 + threadIdx.x;
  if (i < NN) g_deg[i] = 0;
}

__global__ void count_deg_kernel(const int* __restrict__ dst) {
  int e = blockIdx.x * 256 + threadIdx.x;
  if (e < EE) atomicAdd(&g_deg[dst[e]], 1);
}

// Per-block sums of (deg+1) over SCAN_CH-chunks; also computes dinv.
__global__ void __launch_bounds__(256) block_sums_kernel() {
  __shared__ int sh[8];
  const int b = blockIdx.x, t = threadIdx.x;
  int s = 0;
  for (int i = t; i < SCAN_CH; i += 256) {
    int idx = b * SCAN_CH + i;
    int d1 = g_deg[idx] + 1;
    s += d1;
    g_dinv[idx] = rsqrtf((float)d1);
  }
#pragma unroll
  for (int off = 16; off > 0; off >>= 1) s += __shfl_down_sync(0xffffffffu, s, off);
  if ((t & 31) == 0) sh[t >> 5] = s;
  __syncthreads();
  if (t < 8) {
    s = sh[t];
#pragma unroll
    for (int off = 4; off > 0; off >>= 1) s += __shfl_down_sync(0xffu, s, off);
    if (t == 0) g_blocksum[b] = s;
  }
}

__global__ void scan_offsets_kernel() {
  __shared__ int sh[64];
  const int t = threadIdx.x;
  sh[t] = (t < NSCAN_BLK) ? g_blocksum[t] : 0;
  __syncthreads();
  for (int off = 1; off < 64; off <<= 1) {
    int v = (t >= off) ? sh[t - off] : 0;
    __syncthreads();
    sh[t] += v;
    __syncthreads();
  }
  if (t < NSCAN_BLK) g_blockoff[t] = (t == 0) ? 0 : sh[t - 1];
}

__global__ void __launch_bounds__(1024) scan_write_kernel() {
  __shared__ int sh[1024];
  const int b = blockIdx.x, t = threadIdx.x;
  const int idx = b * SCAN_CH + t;
  int v = (t < SCAN_CH) ? g_deg[idx] + 1 : 0;
  sh[t] = v;
  __syncthreads();
  for (int off = 1; off < 1024; off <<= 1) {
    int u = (t >= off) ? sh[t - off] : 0;
    __syncthreads();
    sh[t] += u;
    __syncthreads();
  }
  const int base = g_blockoff[b];
  if (t < SCAN_CH) {
    int p = base + ((t == 0) ? 0 : sh[t - 1]);
    g_rowptr[idx] = p;
    g_cursor[idx] = p;
  }
  if (b == NSCAN_BLK - 1 && t == SCAN_CH - 1) g_rowptr[NN] = base + sh[t];
}

__global__ void fill_csr_kernel(const int* __restrict__ src,
                                const int* __restrict__ dst) {
  int t = blockIdx.x * 256 + threadIdx.x;
  if (t < EE) {
    int s = src[t], d = dst[t];
    int pos = atomicAdd(&g_cursor[d], 1);
    g_adj[pos] = make_int2(s, __float_as_int(g_dinv[s] * g_dinv[d]));
  } else if (t < NNZ) {
    int i = t - EE;
    int pos = atomicAdd(&g_cursor[i], 1);
    float di = g_dinv[i];
    g_adj[pos] = make_int2(i, __float_as_int(di * di));
  }
}

// ---------------- dense: out[N,DOUT] = A[N,K] @ W[K,DOUT] (+bias)(relu) -----
template <int K, int DOUT, bool RELU, bool BIAS>
__global__ void __launch_bounds__(256) gemm_kernel(
    const float* __restrict__ A, const float* __restrict__ W,
    const float* __restrict__ bias, float* __restrict__ out) {
  constexpr int COLT = (DOUT < 64) ? DOUT : 64;
  constexpr int VPT = COLT / 32;   // 1 or 2
  constexpr int KS = K + 4;        // padded stride (words)
  constexpr int R = 8;
  __shared__ __align__(16) float Ws[COLT * KS];

  const int col0 = blockIdx.y * COLT;
  for (int i = threadIdx.x; i < COLT * K; i += 256) {
    int c = i / K, k = i - c * K;
    Ws[c * KS + k] = W[k * DOUT + col0 + c];
  }
  __syncthreads();

  const int lane = threadIdx.x & 31;
  const int row0 = (blockIdx.x * 8 + (threadIdx.x >> 5)) * R;

  ull acc[R][VPT];
#pragma unroll
  for (int r = 0; r < R; r++)
#pragma unroll
    for (int v = 0; v < VPT; v++) acc[r][v] = 0ull;

  const float* a_base = A + (size_t)row0 * K;
#pragma unroll 2
  for (int k = 0; k < K; k += 4) {
    ull w01[VPT], w23[VPT];
#pragma unroll
    for (int v = 0; v < VPT; v++) {
      float4 wv = *reinterpret_cast<const float4*>(&Ws[(lane + 32 * v) * KS + k]);
      w01[v] = reinterpret_cast<ull*>(&wv)[0];
      w23[v] = reinterpret_cast<ull*>(&wv)[1];
    }
#pragma unroll
    for (int r = 0; r < R; r++) {
      float4 av = __ldg(reinterpret_cast<const float4*>(a_base + r * K + k));
      ull a01 = reinterpret_cast<ull*>(&av)[0];
      ull a23 = reinterpret_cast<ull*>(&av)[1];
#pragma unroll
      for (int v = 0; v < VPT; v++) {
        acc[r][v] = ffma2(a01, w01[v], acc[r][v]);
        acc[r][v] = ffma2(a23, w23[v], acc[r][v]);
      }
    }
  }

#pragma unroll
  for (int r = 0; r < R; r++) {
#pragma unroll
    for (int v = 0; v < VPT; v++) {
      float s = hsum2(acc[r][v]);
      int c = col0 + lane + 32 * v;
      if (BIAS) s += __ldg(&bias[c]);
      if (RELU) s = fmaxf(s, 0.0f);
      out[(size_t)(row0 + r) * DOUT + c] = s;
    }
  }
}

// ---------------- fused gemm2+gemm3: t3 = relu(a @ W2 + b2) @ W3 -------------
// a: [N,64], W2: [64,128], W3: [128,128]; out: [N,128]. All weights + the h2
// intermediate staged in shared. 512 threads, 16 warps x 4 rows = 64 rows/blk.
#define F23_S1 68     // Ws1 k-stride (words)
#define F23_S2 132    // Ws2 / h2 k-stride (words)
#define F23_SZ1 (128 * F23_S1)            // 8704 floats
#define F23_SZ2 (128 * F23_S2)            // 16896 floats
#define F23_H2  (16 * 4 * F23_S2)         // 8448 floats
#define F23_SMEM ((F23_SZ1 + F23_SZ2 + F23_H2) * 4)  // 136192 bytes

__global__ void __launch_bounds__(512) fused23_kernel(
    const float* __restrict__ A, const float* __restrict__ W2,
    const float* __restrict__ b2, const float* __restrict__ W3,
    float* __restrict__ out) {
  extern __shared__ __align__(16) float sm[];
  float* Ws1 = sm;                    // [128][F23_S1] : Ws1[c][k] = W2[k][c]
  float* Ws2 = sm + F23_SZ1;          // [128][F23_S2] : Ws2[c][k] = W3[k][c]
  float* H2  = sm + F23_SZ1 + F23_SZ2;

  const int tid = threadIdx.x;
  for (int i = tid; i < 128 * 64; i += 512) {
    int c = i >> 6, k = i & 63;
    Ws1[c * F23_S1 + k] = W2[k * 128 + c];
  }
  for (int i = tid; i < 128 * 128; i += 512) {
    int c = i >> 7, k = i & 127;
    Ws2[c * F23_S2 + k] = W3[k * 128 + c];
  }
  __syncthreads();

  const int lane = tid & 31;
  const int warp = tid >> 5;
  const int row0 = blockIdx.x * 64 + warp * 4;
  float* h2w = H2 + warp * 4 * F23_S2;

  // ---- stage 1: h2 = relu(a @ W2 + b2), rows in warp, cols lane+32v ----
  {
    ull acc[4][4];
#pragma unroll
    for (int r = 0; r < 4; r++)
#pragma unroll
      for (int v = 0; v < 4; v++) acc[r][v] = 0ull;

    const float* a_base = A + (size_t)row0 * 64;
#pragma unroll 2
    for (int k = 0; k < 64; k += 4) {
      ull w01[4], w23[4];
#pragma unroll
      for (int v = 0; v < 4; v++) {
        float4 wv = *reinterpret_cast<const float4*>(&Ws1[(lane + 32 * v) * F23_S1 + k]);
        w01[v] = reinterpret_cast<ull*>(&wv)[0];
        w23[v] = reinterpret_cast<ull*>(&wv)[1];
      }
#pragma unroll
      for (int r = 0; r < 4; r++) {
        float4 av = __ldg(reinterpret_cast<const float4*>(a_base + r * 64 + k));
        ull a01 = reinterpret_cast<ull*>(&av)[0];
        ull a23 = reinterpret_cast<ull*>(&av)[1];
#pragma unroll
        for (int v = 0; v < 4; v++) {
          acc[r][v] = ffma2(a01, w01[v], acc[r][v]);
          acc[r][v] = ffma2(a23, w23[v], acc[r][v]);
        }
      }
    }
#pragma unroll
    for (int r = 0; r < 4; r++)
#pragma unroll
      for (int v = 0; v < 4; v++) {
        int c = lane + 32 * v;
        float s = hsum2(acc[r][v]) + __ldg(&b2[c]);
        h2w[r * F23_S2 + c] = fmaxf(s, 0.0f);
      }
  }
  __syncwarp();

  // ---- stage 2: t3 = h2 @ W3, all operands in shared ----
  {
    ull acc[4][4];
#pragma unroll
    for (int r = 0; r < 4; r++)
#pragma unroll
      for (int v = 0; v < 4; v++) acc[r][v] = 0ull;

#pragma unroll 2
    for (int k = 0; k < 128; k += 4) {
      ull w01[4], w23[4];
#pragma unroll
      for (int v = 0; v < 4; v++) {
        float4 wv = *reinterpret_cast<const float4*>(&Ws2[(lane + 32 * v) * F23_S2 + k]);
        w01[v] = reinterpret_cast<ull*>(&wv)[0];
        w23[v] = reinterpret_cast<ull*>(&wv)[1];
      }
#pragma unroll
      for (int r = 0; r < 4; r++) {
        float4 av = *reinterpret_cast<const float4*>(&h2w[r * F23_S2 + k]);
        ull a01 = reinterpret_cast<ull*>(&av)[0];
        ull a23 = reinterpret_cast<ull*>(&av)[1];
#pragma unroll
        for (int v = 0; v < 4; v++) {
          acc[r][v] = ffma2(a01, w01[v], acc[r][v]);
          acc[r][v] = ffma2(a23, w23[v], acc[r][v]);
        }
      }
    }
#pragma unroll
    for (int r = 0; r < 4; r++)
#pragma unroll
      for (int v = 0; v < 4; v++)
        out[(size_t)(row0 + r) * 128 + lane + 32 * v] = hsum2(acc[r][v]);
  }
}

// ---------------- aggregation: Hout[i] = sum_{e in row i} w[e]*Hin[col[e]] --
// One warp per node, gather-only, packed {col,w} adjacency, f32x2 FMAs.
template <int D, bool RELU, bool BIAS>
__global__ void __launch_bounds__(256) agg_kernel(
    const float* __restrict__ Hin, const float* __restrict__ bias,
    float* __restrict__ Hout) {
  const int node = blockIdx.x * 8 + (threadIdx.x >> 5);
  const int lane = threadIdx.x & 31;
  const int beg = g_rowptr[node];
  const int end = g_rowptr[node + 1];

  if constexpr (D == 128) {
    ull acc01 = 0ull, acc23 = 0ull;
    int e = beg;
    for (; e + 4 <= end; e += 4) {
      int2 a0 = __ldg(&g_adj[e + 0]);
      int2 a1 = __ldg(&g_adj[e + 1]);
      int2 a2 = __ldg(&g_adj[e + 2]);
      int2 a3 = __ldg(&g_adj[e + 3]);
      float4 x0 = __ldg(reinterpret_cast<const float4*>(Hin + (size_t)a0.x * D) + lane);
      float4 x1 = __ldg(reinterpret_cast<const float4*>(Hin + (size_t)a1.x * D) + lane);
      float4 x2 = __ldg(reinterpret_cast<const float4*>(Hin + (size_t)a2.x * D) + lane);
      float4 x3 = __ldg(reinterpret_cast<const float4*>(Hin + (size_t)a3.x * D) + lane);
      float w0 = __int_as_float(a0.y), w1 = __int_as_float(a1.y);
      float w2 = __int_as_float(a2.y), w3 = __int_as_float(a3.y);
      ull ww0 = pack2(w0, w0), ww1 = pack2(w1, w1);
      ull ww2 = pack2(w2, w2), ww3 = pack2(w3, w3);
      acc01 = ffma2(reinterpret_cast<ull*>(&x0)[0], ww0, acc01);
      acc23 = ffma2(reinterpret_cast<ull*>(&x0)[1], ww0, acc23);
      acc01 = ffma2(reinterpret_cast<ull*>(&x1)[0], ww1, acc01);
      acc23 = ffma2(reinterpret_cast<ull*>(&x1)[1], ww1, acc23);
      acc01 = ffma2(reinterpret_cast<ull*>(&x2)[0], ww2, acc01);
      acc23 = ffma2(reinterpret_cast<ull*>(&x2)[1], ww2, acc23);
      acc01 = ffma2(reinterpret_cast<ull*>(&x3)[0], ww3, acc01);
      acc23 = ffma2(reinterpret_cast<ull*>(&x3)[1], ww3, acc23);
    }
    for (; e < end; e++) {
      int2 a0 = __ldg(&g_adj[e]);
      float w0 = __int_as_float(a0.y);
      ull ww0 = pack2(w0, w0);
      float4 x0 = __ldg(reinterpret_cast<const float4*>(Hin + (size_t)a0.x * D) + lane);
      acc01 = ffma2(reinterpret_cast<ull*>(&x0)[0], ww0, acc01);
      acc23 = ffma2(reinterpret_cast<ull*>(&x0)[1], ww0, acc23);
    }
    float4 acc;
    acc.x = __int_as_float((int)(acc01 & 0xffffffffull));
    acc.y = __int_as_float((int)(acc01 >> 32));
    acc.z = __int_as_float((int)(acc23 & 0xffffffffull));
    acc.w = __int_as_float((int)(acc23 >> 32));
    if (BIAS) {
      float4 b = __ldg(reinterpret_cast<const float4*>(bias) + lane);
      acc.x += b.x; acc.y += b.y; acc.z += b.z; acc.w += b.w;
    }
    if (RELU) {
      acc.x = fmaxf(acc.x, 0.f); acc.y = fmaxf(acc.y, 0.f);
      acc.z = fmaxf(acc.z, 0.f); acc.w = fmaxf(acc.w, 0.f);
    }
    reinterpret_cast<float4*>(Hout + (size_t)node * D)[lane] = acc;
  } else {  // D == 64
    ull acc01 = 0ull;
    int e = beg;
    for (; e + 4 <= end; e += 4) {
      int2 a0 = __ldg(&g_adj[e + 0]);
      int2 a1 = __ldg(&g_adj[e + 1]);
      int2 a2 = __ldg(&g_adj[e + 2]);
      int2 a3 = __ldg(&g_adj[e + 3]);
      float2 x0 = __ldg(reinterpret_cast<const float2*>(Hin + (size_t)a0.x * D) + lane);
      float2 x1 = __ldg(reinterpret_cast<const float2*>(Hin + (size_t)a1.x * D) + lane);
      float2 x2 = __ldg(reinterpret_cast<const float2*>(Hin + (size_t)a2.x * D) + lane);
      float2 x3 = __ldg(reinterpret_cast<const float2*>(Hin + (size_t)a3.x * D) + lane);
      float w0 = __int_as_float(a0.y), w1 = __int_as_float(a1.y);
      float w2 = __int_as_float(a2.y), w3 = __int_as_float(a3.y);
      acc01 = ffma2(*reinterpret_cast<ull*>(&x0), pack2(w0, w0), acc01);
      acc01 = ffma2(*reinterpret_cast<ull*>(&x1), pack2(w1, w1), acc01);
      acc01 = ffma2(*reinterpret_cast<ull*>(&x2), pack2(w2, w2), acc01);
      acc01 = ffma2(*reinterpret_cast<ull*>(&x3), pack2(w3, w3), acc01);
    }
    for (; e < end; e++) {
      int2 a0 = __ldg(&g_adj[e]);
      float w0 = __int_as_float(a0.y);
      float2 x0 = __ldg(reinterpret_cast<const float2*>(Hin + (size_t)a0.x * D) + lane);
      acc01 = ffma2(*reinterpret_cast<ull*>(&x0), pack2(w0, w0), acc01);
    }
    float2 acc;
    acc.x = __int_as_float((int)(acc01 & 0xffffffffull));
    acc.y = __int_as_float((int)(acc01 >> 32));
    if (BIAS) {
      float2 b = __ldg(reinterpret_cast<const float2*>(bias) + lane);
      acc.x += b.x; acc.y += b.y;
    }
    if (RELU) { acc.x = fmaxf(acc.x, 0.f); acc.y = fmaxf(acc.y, 0.f); }
    reinterpret_cast<float2*>(Hout + (size_t)node * D)[lane] = acc;
  }
}

// ---------------- launch ------------------------------------------------------
extern "C" void kernel_launch(void* const* d_in, const int* in_sizes, int n_in,
                              void* d_out, int out_size) {
  (void)in_sizes; (void)n_in; (void)out_size;
  const float* x  = (const float*)d_in[0];
  const int*   ei = (const int*)d_in[1];
  const int* src = ei;
  const int* dst = ei + EE;
  const float* W1 = (const float*)d_in[3];
  const float* b1 = (const float*)d_in[4];
  const float* W2 = (const float*)d_in[5];
  const float* b2 = (const float*)d_in[6];
  const float* W3 = (const float*)d_in[7];
  const float* b3 = (const float*)d_in[8];
  const float* W4 = (const float*)d_in[9];
  const float* b4 = (const float*)d_in[10];
  const float* Wl = (const float*)d_in[11];
  const float* bl = (const float*)d_in[12];
  float* out = (float*)d_out;

  float *buf0, *buf1;
  cudaGetSymbolAddress((void**)&buf0, g_buf0);
  cudaGetSymbolAddress((void**)&buf1, g_buf1);

  // One-time infra (host objects only; no device allocation).
  static cudaStream_t s_prep = nullptr;
  static cudaEvent_t ev_fork = nullptr, ev_join = nullptr;
  if (s_prep == nullptr) {
    cudaStreamCreateWithFlags(&s_prep, cudaStreamNonBlocking);
    cudaEventCreateWithFlags(&ev_fork, cudaEventDisableTiming);
    cudaEventCreateWithFlags(&ev_join, cudaEventDisableTiming);
    cudaFuncSetAttribute(fused23_kernel,
                         cudaFuncAttributeMaxDynamicSharedMemorySize, F23_SMEM);
  }

  // ---- fork: CSR prep (depends only on edge_index) runs on s_prep,
  //      concurrently with gemm1 (depends only on x, W1) on the main stream.
  cudaEventRecord(ev_fork, 0);
  cudaStreamWaitEvent(s_prep, ev_fork, 0);

  init_deg_kernel<<<(NN + 255) / 256, 256, 0, s_prep>>>();
  count_deg_kernel<<<(EE + 255) / 256, 256, 0, s_prep>>>(dst);
  block_sums_kernel<<<NSCAN_BLK, 256, 0, s_prep>>>();
  scan_offsets_kernel<<<1, 64, 0, s_prep>>>();
  scan_write_kernel<<<NSCAN_BLK, 1024, 0, s_prep>>>();
  fill_csr_kernel<<<(NNZ + 255) / 256, 256, 0, s_prep>>>(src, dst);
  cudaEventRecord(ev_join, s_prep);

  const int GEMM_BLOCKS = NN / 64;  // 625
  const int AGG_BLOCKS = NN / 8;    // 5000

  // L1 GEMM overlaps prep: t = x @ W1
  gemm_kernel<128, 64, false, false><<<dim3(GEMM_BLOCKS, 1), 256>>>(x, W1, nullptr, buf0);

  cudaStreamWaitEvent(0, ev_join, 0);  // join: aggs need the CSR

  // h1 = relu(agg(t) + b1)
  agg_kernel<64, true, true><<<AGG_BLOCKS, 256>>>(buf0, b1, buf1);
  // L2 agg-first: a = agg(h1)
  agg_kernel<64, false, false><<<AGG_BLOCKS, 256>>>(buf1, nullptr, buf0);
  // fused L2-gemm + L3-gemm: t3 = relu(a @ W2 + b2) @ W3
  fused23_kernel<<<GEMM_BLOCKS, 512, F23_SMEM>>>(buf0, W2, b2, W3, buf1);
  // h3 = relu(agg(t3) + b3)
  agg_kernel<128, true, true><<<AGG_BLOCKS, 256>>>(buf1, b3, buf0);
  // L4: t = h3 @ W4 ; h4 = relu(agg(t) + b4)
  gemm_kernel<128, 64, false, false><<<dim3(GEMM_BLOCKS, 1), 256>>>(buf0, W4, nullptr, buf1);
  agg_kernel<64, true, true><<<AGG_BLOCKS, 256>>>(buf1, b4, buf0);
  // Head: out = h4 @ Wl + bl
  gemm_kernel<64, 32, false, true><<<dim3(GEMM_BLOCKS, 1), 256>>>(buf0, Wl, bl, out);
}

// round 6
// speedup vs baseline: 1.0300x; 1.0300x over previous
#include <cuda_runtime.h>
#include <cstdint>

#define NN  40000
#define EE  640000
#define NNZ (EE + NN)   // 680000 (edges + self-loops)

#define NSCAN_BLK 40    // 40 blocks x 1000 elements = NN
#define SCAN_CH   1000

typedef unsigned long long ull;

// ---------------- scratch (device globals — no runtime allocation) ----------
__device__ __align__(256) float g_buf0[NN * 128];
__device__ __align__(256) float g_buf1[NN * 128];
__device__ float g_dinv[NN];
__device__ int   g_deg[NN];
__device__ int   g_rowptr[NN + 1];
__device__ int   g_cursor[NN];
__device__ __align__(16) int2 g_adj[NNZ];   // {col, bitcast(weight)}
__device__ int   g_blocksum[NSCAN_BLK];
__device__ int   g_blockoff[NSCAN_BLK];

// ---------------- packed fp32x2 helpers (sm_10x) -----------------------------
__device__ __forceinline__ ull ffma2(ull a, ull b, ull c) {
  ull d;
  asm("fma.rn.f32x2 %0, %1, %2, %3;" : "=l"(d) : "l"(a), "l"(b), "l"(c));
  return d;
}
__device__ __forceinline__ float hsum2(ull v) {
  float lo, hi;
  asm("mov.b64 {%0, %1}, %2;" : "=f"(lo), "=f"(hi) : "l"(v));
  return lo + hi;
}
__device__ __forceinline__ ull pack2(float lo, float hi) {
  ull v;
  asm("mov.b64 %0, {%1, %2};" : "=l"(v) : "f"(lo), "f"(hi));
  return v;
}

// ---------------- preprocessing ---------------------------------------------
__global__ void init_deg_kernel() {
  int i = blockIdx.x * 256 + threadIdx.x;
  if (i < NN) g_deg[i] = 0;
}

__global__ void count_deg_kernel(const int* __restrict__ dst) {
  int e = blockIdx.x * 256 + threadIdx.x;
  if (e < EE) atomicAdd(&g_deg[dst[e]], 1);
}

// Per-block sums of (deg+1) over SCAN_CH-chunks; also computes dinv.
__global__ void __launch_bounds__(256) block_sums_kernel() {
  __shared__ int sh[8];
  const int b = blockIdx.x, t = threadIdx.x;
  int s = 0;
  for (int i = t; i < SCAN_CH; i += 256) {
    int idx = b * SCAN_CH + i;
    int d1 = g_deg[idx] + 1;
    s += d1;
    g_dinv[idx] = rsqrtf((float)d1);
  }
#pragma unroll
  for (int off = 16; off > 0; off >>= 1) s += __shfl_down_sync(0xffffffffu, s, off);
  if ((t & 31) == 0) sh[t >> 5] = s;
  __syncthreads();
  if (t < 8) {
    s = sh[t];
#pragma unroll
    for (int off = 4; off > 0; off >>= 1) s += __shfl_down_sync(0xffu, s, off);
    if (t == 0) g_blocksum[b] = s;
  }
}

__global__ void scan_offsets_kernel() {
  __shared__ int sh[64];
  const int t = threadIdx.x;
  sh[t] = (t < NSCAN_BLK) ? g_blocksum[t] : 0;
  __syncthreads();
  for (int off = 1; off < 64; off <<= 1) {
    int v = (t >= off) ? sh[t - off] : 0;
    __syncthreads();
    sh[t] += v;
    __syncthreads();
  }
  if (t < NSCAN_BLK) g_blockoff[t] = (t == 0) ? 0 : sh[t - 1];
}

__global__ void __launch_bounds__(1024) scan_write_kernel() {
  __shared__ int sh[1024];
  const int b = blockIdx.x, t = threadIdx.x;
  const int idx = b * SCAN_CH + t;
  int v = (t < SCAN_CH) ? g_deg[idx] + 1 : 0;
  sh[t] = v;
  __syncthreads();
  for (int off = 1; off < 1024; off <<= 1) {
    int u = (t >= off) ? sh[t - off] : 0;
    __syncthreads();
    sh[t] += u;
    __syncthreads();
  }
  const int base = g_blockoff[b];
  if (t < SCAN_CH) {
    int p = base + ((t == 0) ? 0 : sh[t - 1]);
    g_rowptr[idx] = p;
    g_cursor[idx] = p;
  }
  if (b == NSCAN_BLK - 1 && t == SCAN_CH - 1) g_rowptr[NN] = base + sh[t];
}

__global__ void fill_csr_kernel(const int* __restrict__ src,
                                const int* __restrict__ dst) {
  int t = blockIdx.x * 256 + threadIdx.x;
  if (t < EE) {
    int s = src[t], d = dst[t];
    int pos = atomicAdd(&g_cursor[d], 1);
    g_adj[pos] = make_int2(s, __float_as_int(g_dinv[s] * g_dinv[d]));
  } else if (t < NNZ) {
    int i = t - EE;
    int pos = atomicAdd(&g_cursor[i], 1);
    float di = g_dinv[i];
    g_adj[pos] = make_int2(i, __float_as_int(di * di));
  }
}

// ---------------- dense: out[N,DOUT] = A[N,K] @ W[K,DOUT] (+bias)(relu) -----
template <int K, int DOUT, bool RELU, bool BIAS>
__global__ void __launch_bounds__(256) gemm_kernel(
    const float* __restrict__ A, const float* __restrict__ W,
    const float* __restrict__ bias, float* __restrict__ out) {
  constexpr int COLT = (DOUT < 64) ? DOUT : 64;
  constexpr int VPT = COLT / 32;   // 1 or 2
  constexpr int KS = K + 4;        // padded stride (words)
  constexpr int R = 8;
  __shared__ __align__(16) float Ws[COLT * KS];

  const int col0 = blockIdx.y * COLT;
  for (int i = threadIdx.x; i < COLT * K; i += 256) {
    int c = i / K, k = i - c * K;
    Ws[c * KS + k] = W[k * DOUT + col0 + c];
  }
  __syncthreads();

  const int lane = threadIdx.x & 31;
  const int row0 = (blockIdx.x * 8 + (threadIdx.x >> 5)) * R;

  ull acc[R][VPT];
#pragma unroll
  for (int r = 0; r < R; r++)
#pragma unroll
    for (int v = 0; v < VPT; v++) acc[r][v] = 0ull;

  const float* a_base = A + (size_t)row0 * K;
#pragma unroll 2
  for (int k = 0; k < K; k += 4) {
    ull w01[VPT], w23[VPT];
#pragma unroll
    for (int v = 0; v < VPT; v++) {
      float4 wv = *reinterpret_cast<const float4*>(&Ws[(lane + 32 * v) * KS + k]);
      w01[v] = reinterpret_cast<ull*>(&wv)[0];
      w23[v] = reinterpret_cast<ull*>(&wv)[1];
    }
#pragma unroll
    for (int r = 0; r < R; r++) {
      float4 av = __ldg(reinterpret_cast<const float4*>(a_base + r * K + k));
      ull a01 = reinterpret_cast<ull*>(&av)[0];
      ull a23 = reinterpret_cast<ull*>(&av)[1];
#pragma unroll
      for (int v = 0; v < VPT; v++) {
        acc[r][v] = ffma2(a01, w01[v], acc[r][v]);
        acc[r][v] = ffma2(a23, w23[v], acc[r][v]);
      }
    }
  }

#pragma unroll
  for (int r = 0; r < R; r++) {
#pragma unroll
    for (int v = 0; v < VPT; v++) {
      float s = hsum2(acc[r][v]);
      int c = col0 + lane + 32 * v;
      if (BIAS) s += __ldg(&bias[c]);
      if (RELU) s = fmaxf(s, 0.0f);
      out[(size_t)(row0 + r) * DOUT + c] = s;
    }
  }
}

// ---------------- aggregation (D=128): one warp per node ---------------------
template <bool RELU, bool BIAS>
__global__ void __launch_bounds__(256) agg128_kernel(
    const float* __restrict__ Hin, const float* __restrict__ bias,
    float* __restrict__ Hout) {
  const int node = blockIdx.x * 8 + (threadIdx.x >> 5);
  const int lane = threadIdx.x & 31;
  const int beg = g_rowptr[node];
  const int end = g_rowptr[node + 1];

  ull acc01 = 0ull, acc23 = 0ull;
  int e = beg;
  for (; e + 4 <= end; e += 4) {
    int2 a0 = __ldg(&g_adj[e + 0]);
    int2 a1 = __ldg(&g_adj[e + 1]);
    int2 a2 = __ldg(&g_adj[e + 2]);
    int2 a3 = __ldg(&g_adj[e + 3]);
    float4 x0 = __ldg(reinterpret_cast<const float4*>(Hin + (size_t)a0.x * 128) + lane);
    float4 x1 = __ldg(reinterpret_cast<const float4*>(Hin + (size_t)a1.x * 128) + lane);
    float4 x2 = __ldg(reinterpret_cast<const float4*>(Hin + (size_t)a2.x * 128) + lane);
    float4 x3 = __ldg(reinterpret_cast<const float4*>(Hin + (size_t)a3.x * 128) + lane);
    ull ww0 = pack2(__int_as_float(a0.y), __int_as_float(a0.y));
    ull ww1 = pack2(__int_as_float(a1.y), __int_as_float(a1.y));
    ull ww2 = pack2(__int_as_float(a2.y), __int_as_float(a2.y));
    ull ww3 = pack2(__int_as_float(a3.y), __int_as_float(a3.y));
    acc01 = ffma2(reinterpret_cast<ull*>(&x0)[0], ww0, acc01);
    acc23 = ffma2(reinterpret_cast<ull*>(&x0)[1], ww0, acc23);
    acc01 = ffma2(reinterpret_cast<ull*>(&x1)[0], ww1, acc01);
    acc23 = ffma2(reinterpret_cast<ull*>(&x1)[1], ww1, acc23);
    acc01 = ffma2(reinterpret_cast<ull*>(&x2)[0], ww2, acc01);
    acc23 = ffma2(reinterpret_cast<ull*>(&x2)[1], ww2, acc23);
    acc01 = ffma2(reinterpret_cast<ull*>(&x3)[0], ww3, acc01);
    acc23 = ffma2(reinterpret_cast<ull*>(&x3)[1], ww3, acc23);
  }
  for (; e < end; e++) {
    int2 a0 = __ldg(&g_adj[e]);
    ull ww0 = pack2(__int_as_float(a0.y), __int_as_float(a0.y));
    float4 x0 = __ldg(reinterpret_cast<const float4*>(Hin + (size_t)a0.x * 128) + lane);
    acc01 = ffma2(reinterpret_cast<ull*>(&x0)[0], ww0, acc01);
    acc23 = ffma2(reinterpret_cast<ull*>(&x0)[1], ww0, acc23);
  }
  float4 acc;
  acc.x = __int_as_float((int)(acc01 & 0xffffffffull));
  acc.y = __int_as_float((int)(acc01 >> 32));
  acc.z = __int_as_float((int)(acc23 & 0xffffffffull));
  acc.w = __int_as_float((int)(acc23 >> 32));
  if (BIAS) {
    float4 b = __ldg(reinterpret_cast<const float4*>(bias) + lane);
    acc.x += b.x; acc.y += b.y; acc.z += b.z; acc.w += b.w;
  }
  if (RELU) {
    acc.x = fmaxf(acc.x, 0.f); acc.y = fmaxf(acc.y, 0.f);
    acc.z = fmaxf(acc.z, 0.f); acc.w = fmaxf(acc.w, 0.f);
  }
  reinterpret_cast<float4*>(Hout + (size_t)node * 128)[lane] = acc;
}

// ---------------- aggregation (D=64): HALF-warp per node ---------------------
// 16 lanes x float4 = one 64-float row; each warp serves 2 nodes -> 2x the
// outstanding gathers per scheduler slot vs the warp-per-node float2 version.
template <bool RELU, bool BIAS>
__global__ void __launch_bounds__(256) agg64_kernel(
    const float* __restrict__ Hin, const float* __restrict__ bias,
    float* __restrict__ Hout) {
  const int node = blockIdx.x * 16 + (threadIdx.x >> 4);
  const int sub = threadIdx.x & 15;
  const int beg = g_rowptr[node];
  const int end = g_rowptr[node + 1];

  ull acc01 = 0ull, acc23 = 0ull;
  int e = beg;
  for (; e + 4 <= end; e += 4) {
    int2 a0 = __ldg(&g_adj[e + 0]);
    int2 a1 = __ldg(&g_adj[e + 1]);
    int2 a2 = __ldg(&g_adj[e + 2]);
    int2 a3 = __ldg(&g_adj[e + 3]);
    float4 x0 = __ldg(reinterpret_cast<const float4*>(Hin + (size_t)a0.x * 64) + sub);
    float4 x1 = __ldg(reinterpret_cast<const float4*>(Hin + (size_t)a1.x * 64) + sub);
    float4 x2 = __ldg(reinterpret_cast<const float4*>(Hin + (size_t)a2.x * 64) + sub);
    float4 x3 = __ldg(reinterpret_cast<const float4*>(Hin + (size_t)a3.x * 64) + sub);
    ull ww0 = pack2(__int_as_float(a0.y), __int_as_float(a0.y));
    ull ww1 = pack2(__int_as_float(a1.y), __int_as_float(a1.y));
    ull ww2 = pack2(__int_as_float(a2.y), __int_as_float(a2.y));
    ull ww3 = pack2(__int_as_float(a3.y), __int_as_float(a3.y));
    acc01 = ffma2(reinterpret_cast<ull*>(&x0)[0], ww0, acc01);
    acc23 = ffma2(reinterpret_cast<ull*>(&x0)[1], ww0, acc23);
    acc01 = ffma2(reinterpret_cast<ull*>(&x1)[0], ww1, acc01);
    acc23 = ffma2(reinterpret_cast<ull*>(&x1)[1], ww1, acc23);
    acc01 = ffma2(reinterpret_cast<ull*>(&x2)[0], ww2, acc01);
    acc23 = ffma2(reinterpret_cast<ull*>(&x2)[1], ww2, acc23);
    acc01 = ffma2(reinterpret_cast<ull*>(&x3)[0], ww3, acc01);
    acc23 = ffma2(reinterpret_cast<ull*>(&x3)[1], ww3, acc23);
  }
  for (; e < end; e++) {
    int2 a0 = __ldg(&g_adj[e]);
    ull ww0 = pack2(__int_as_float(a0.y), __int_as_float(a0.y));
    float4 x0 = __ldg(reinterpret_cast<const float4*>(Hin + (size_t)a0.x * 64) + sub);
    acc01 = ffma2(reinterpret_cast<ull*>(&x0)[0], ww0, acc01);
    acc23 = ffma2(reinterpret_cast<ull*>(&x0)[1], ww0, acc23);
  }
  float4 acc;
  acc.x = __int_as_float((int)(acc01 & 0xffffffffull));
  acc.y = __int_as_float((int)(acc01 >> 32));
  acc.z = __int_as_float((int)(acc23 & 0xffffffffull));
  acc.w = __int_as_float((int)(acc23 >> 32));
  if (BIAS) {
    float4 b = __ldg(reinterpret_cast<const float4*>(bias) + sub);
    acc.x += b.x; acc.y += b.y; acc.z += b.z; acc.w += b.w;
  }
  if (RELU) {
    acc.x = fmaxf(acc.x, 0.f); acc.y = fmaxf(acc.y, 0.f);
    acc.z = fmaxf(acc.z, 0.f); acc.w = fmaxf(acc.w, 0.f);
  }
  reinterpret_cast<float4*>(Hout + (size_t)node * 64)[sub] = acc;
}

// ---------------- launch ------------------------------------------------------
extern "C" void kernel_launch(void* const* d_in, const int* in_sizes, int n_in,
                              void* d_out, int out_size) {
  (void)in_sizes; (void)n_in; (void)out_size;
  const float* x  = (const float*)d_in[0];
  const int*   ei = (const int*)d_in[1];
  const int* src = ei;
  const int* dst = ei + EE;
  const float* W1 = (const float*)d_in[3];
  const float* b1 = (const float*)d_in[4];
  const float* W2 = (const float*)d_in[5];
  const float* b2 = (const float*)d_in[6];
  const float* W3 = (const float*)d_in[7];
  const float* b3 = (const float*)d_in[8];
  const float* W4 = (const float*)d_in[9];
  const float* b4 = (const float*)d_in[10];
  const float* Wl = (const float*)d_in[11];
  const float* bl = (const float*)d_in[12];
  float* out = (float*)d_out;

  float *buf0, *buf1;
  cudaGetSymbolAddress((void**)&buf0, g_buf0);
  cudaGetSymbolAddress((void**)&buf1, g_buf1);

  // One-time infra (host objects only; no device allocation).
  static cudaStream_t s_prep = nullptr;
  static cudaEvent_t ev_fork = nullptr, ev_join = nullptr;
  if (s_prep == nullptr) {
    cudaStreamCreateWithFlags(&s_prep, cudaStreamNonBlocking);
    cudaEventCreateWithFlags(&ev_fork, cudaEventDisableTiming);
    cudaEventCreateWithFlags(&ev_join, cudaEventDisableTiming);
  }

  // ---- fork: CSR prep (depends only on edge_index) on s_prep, concurrent
  //      with gemm1 (depends only on x, W1) on the main stream.
  cudaEventRecord(ev_fork, 0);
  cudaStreamWaitEvent(s_prep, ev_fork, 0);

  init_deg_kernel<<<(NN + 255) / 256, 256, 0, s_prep>>>();
  count_deg_kernel<<<(EE + 255) / 256, 256, 0, s_prep>>>(dst);
  block_sums_kernel<<<NSCAN_BLK, 256, 0, s_prep>>>();
  scan_offsets_kernel<<<1, 64, 0, s_prep>>>();
  scan_write_kernel<<<NSCAN_BLK, 1024, 0, s_prep>>>();
  fill_csr_kernel<<<(NNZ + 255) / 256, 256, 0, s_prep>>>(src, dst);
  cudaEventRecord(ev_join, s_prep);

  const int GEMM_BLOCKS = NN / 64;    // 625
  const int AGG128_BLOCKS = NN / 8;   // 5000 (warp per node)
  const int AGG64_BLOCKS = NN / 16;   // 2500 (half-warp per node)

  // L1 GEMM overlaps prep: t = x @ W1
  gemm_kernel<128, 64, false, false><<<dim3(GEMM_BLOCKS, 1), 256>>>(x, W1, nullptr, buf0);

  cudaStreamWaitEvent(0, ev_join, 0);  // join: aggs need the CSR

  // h1 = relu(agg(t) + b1)
  agg64_kernel<true, true><<<AGG64_BLOCKS, 256>>>(buf0, b1, buf1);
  // L2 agg-first: a = agg(h1)
  agg64_kernel<false, false><<<AGG64_BLOCKS, 256>>>(buf1, nullptr, buf0);
  // h2 = relu(a @ W2 + b2)
  gemm_kernel<64, 128, true, true><<<dim3(GEMM_BLOCKS, 2), 256>>>(buf0, W2, b2, buf1);
  // t3 = h2 @ W3
  gemm_kernel<128, 128, false, false><<<dim3(GEMM_BLOCKS, 2), 256>>>(buf1, W3, nullptr, buf0);
  // h3 = relu(agg(t3) + b3)
  agg128_kernel<true, true><<<AGG128_BLOCKS, 256>>>(buf0, b3, buf1);
  // L4: t = h3 @ W4 ; h4 = relu(agg(t) + b4)
  gemm_kernel<128, 64, false, false><<<dim3(GEMM_BLOCKS, 1), 256>>>(buf1, W4, nullptr, buf0);
  agg64_kernel<true, true><<<AGG64_BLOCKS, 256>>>(buf0, b4, buf1);
  // Head: out = h4 @ Wl + bl
  gemm_kernel<64, 32, false, true><<<dim3(GEMM_BLOCKS, 1), 256>>>(buf1, Wl, bl, out);
}